// round 3
// baseline (speedup 1.0000x reference)
#include <cuda_runtime.h>

// IDWT_2D reference semantics (raw reshape, NOT standard interleave):
//   x: (B=8, C4=256, H=128, W=128) fp32; C4 = 4 subbands (k) x 64 channels (c)
//   out: (8, 64, 256, 256) where
//     out[b][c][2i + (j>=64)][4*(j%64) + 2a + bb] = sum_k filters[k][0][a][bb] * x[b][k*64+c][i][j]
//
// Pure memory-bound: 128 MiB in + 128 MiB out. Per thread: 4 float4 loads
// (one per subband, coalesced), 4 consecutive float4 stores (64B contiguous).

#define BDIM 256

__global__ void __launch_bounds__(BDIM) idwt2d_kernel(
    const float4* __restrict__ x,      // input as float4
    const float*  __restrict__ filt,   // 16 coeffs: [k][a][bb] -> k*4 + a*2 + bb
    float4*       __restrict__ out)    // output as float4
{
    const int idx = blockIdx.x * BDIM + threadIdx.x;
    // idx = ((b*64 + c)*128 + i)*32 + jq ; input cols 4jq..4jq+3
    const int jq = idx & 31;
    int t = idx >> 5;
    const int i  = t & 127;
    t >>= 7;
    const int c  = t & 63;
    const int b  = t >> 6;

    // Input float4 index: x[b][k*64+c][i][jq]; per-channel plane = 128*32 = 4096 float4
    const int base  = (b * 256 + c) * 4096 + i * 32 + jq;
    const int plane = 64 * 4096;       // subband stride (float4 units)

    const float4 ll = x[base];
    const float4 lh = x[base +     plane];
    const float4 hl = x[base + 2 * plane];
    const float4 hh = x[base + 3 * plane];

    float fk[16];
#pragma unroll
    for (int q = 0; q < 16; q++) fk[q] = __ldg(filt + q);

    float v[4][4];
    v[0][0] = ll.x; v[0][1] = ll.y; v[0][2] = ll.z; v[0][3] = ll.w;
    v[1][0] = lh.x; v[1][1] = lh.y; v[1][2] = lh.z; v[1][3] = lh.w;
    v[2][0] = hl.x; v[2][1] = hl.y; v[2][2] = hl.z; v[2][3] = hl.w;
    v[3][0] = hh.x; v[3][1] = hh.y; v[3][2] = hh.z; v[3][3] = hh.w;

    // Output row r = 2i + (jq>=16); columns 16*(jq&15) .. +15 (16 floats = 4 float4).
    const int r     = 2 * i + (jq >> 4);
    const int colq  = 4 * (jq & 15);               // float4 column index
    const int ob    = ((b * 64 + c) * 256 + r) * 64 + colq;

#pragma unroll
    for (int l = 0; l < 4; l++) {                  // local column (j = 4jq + l)
        float o[4];                                // index m = 2a + bb
#pragma unroll
        for (int m = 0; m < 4; m++) {
            float acc = v[0][l] * fk[m];
#pragma unroll
            for (int k = 1; k < 4; k++)
                acc = fmaf(v[k][l], fk[k * 4 + m], acc);
            o[m] = acc;
        }
        out[ob + l] = make_float4(o[0], o[1], o[2], o[3]);
    }
}

extern "C" void kernel_launch(void* const* d_in, const int* in_sizes, int n_in,
                              void* d_out, int out_size)
{
    const float4* x    = (const float4*)d_in[0];
    const float*  filt = (const float*)d_in[1];
    float4*       out  = (float4*)d_out;

    const int total  = 8 * 64 * 128 * 32;   // 2,097,152 threads
    const int blocks = total / BDIM;        // 8192

    idwt2d_kernel<<<blocks, BDIM>>>(x, filt, out);
}

// round 5
// speedup vs baseline: 1.0444x; 1.0444x over previous
#include <cuda_runtime.h>

// IDWT_2D (raw-reshape semantics):
//   x: (B=8, C4=256, H=128, W=128) fp32; C4 = 4 subbands (k) x 64 channels (c)
//   out[b][c][2i + (j>=64)][4*(j%64) + m] = sum_k filters[k][0][m>>1][m&1] * x[b][k*64+c][i][j]
//
// One thread per OUTPUT float4 (= one input site (i,j), all 4 combos m):
//   loads: 4x LDG.32, lane-consecutive j -> one 128B line per warp per subband
//   store: 1x STG.128, lane-contiguous   -> perfect 512B per warp per instr
// Streaming (.cs) hints: zero reuse, don't pollute L2.

#define BDIM 256

__global__ void __launch_bounds__(BDIM) idwt2d_kernel(
    const float* __restrict__ x,
    const float* __restrict__ filt,    // 16 coeffs: [k][a][bb] -> k*4 + a*2 + bb
    float4*      __restrict__ out)
{
    const int idx = blockIdx.x * BDIM + threadIdx.x;
    // idx = ((b*64 + c)*128 + i)*128 + j
    const int j = idx & 127;
    int t = idx >> 7;
    const int i = t & 127;
    t >>= 7;
    const int c = t & 63;
    const int b = t >> 6;

    // Input scalar index: x[b][k*64+c][i][j]; subband plane stride = 64*128*128
    const int base  = ((b * 256 + c) * 128 + i) * 128 + j;
    const int plane = 64 * 128 * 128;

    const float v0 = __ldcs(x + base);
    const float v1 = __ldcs(x + base +     plane);
    const float v2 = __ldcs(x + base + 2 * plane);
    const float v3 = __ldcs(x + base + 3 * plane);

    float fk[16];
#pragma unroll
    for (int q = 0; q < 16; q++) fk[q] = __ldg(filt + q);

    float o[4];
#pragma unroll
    for (int m = 0; m < 4; m++) {
        float acc = v0 * fk[m];
        acc = fmaf(v1, fk[4 + m], acc);
        acc = fmaf(v2, fk[8 + m], acc);
        acc = fmaf(v3, fk[12 + m], acc);
        o[m] = acc;
    }

    // Output row r = 2i + (j>=64); float4 column = j & 63.
    const int r  = 2 * i + (j >> 6);
    const int ob = ((b * 64 + c) * 256 + r) * 64 + (j & 63);

    const float4 res = make_float4(o[0], o[1], o[2], o[3]);
    __stcs(out + ob, res);
}

extern "C" void kernel_launch(void* const* d_in, const int* in_sizes, int n_in,
                              void* d_out, int out_size)
{
    const float*  x    = (const float*)d_in[0];
    const float*  filt = (const float*)d_in[1];
    float4*       out  = (float4*)d_out;

    const int total  = 8 * 64 * 128 * 128;  // 8,388,608 threads (one per output float4)
    const int blocks = total / BDIM;        // 32768

    idwt2d_kernel<<<blocks, BDIM>>>(x, filt, out);
}

// round 6
// speedup vs baseline: 1.1070x; 1.0599x over previous
#include <cuda_runtime.h>

// IDWT_2D (raw-reshape semantics):
//   x: (B=8, C4=256, H=128, W=128) fp32; C4 = 4 subbands (k) x 64 channels (c)
//   out[b][c][2i + (j>=64)][4*(j%64) + m] = sum_k filters[k][0][m>>1][m&1] * x[b][k*64+c][i][j]
//
// One thread per output float4, ITEMS=2 sites per thread (far-strided by
// total/2) to double memory-level parallelism: 8 scalar loads in flight,
// then 2 lane-contiguous STG.128. Streaming hints (.cs): zero reuse.

#define BDIM  256
#define ITEMS 2
#define TOTAL (8 * 64 * 128 * 128)          // output float4 count
#define HALF  (TOTAL / ITEMS)

__global__ void __launch_bounds__(BDIM) idwt2d_kernel(
    const float* __restrict__ x,
    const float* __restrict__ filt,          // 16 coeffs: [k][a][bb] -> k*4+a*2+bb
    float4*      __restrict__ out)
{
    const int tid = blockIdx.x * BDIM + threadIdx.x;

    float fk[16];
#pragma unroll
    for (int q = 0; q < 16; q++) fk[q] = __ldg(filt + q);

    int base[ITEMS];
    int ob[ITEMS];
    float v[ITEMS][4];

    // Address generation + all loads issued front-batched (MLP = 8)
#pragma unroll
    for (int s = 0; s < ITEMS; s++) {
        const int idx = tid + s * HALF;      // idx = ((b*64+c)*128 + i)*128 + j
        const int j = idx & 127;
        int t = idx >> 7;
        const int i = t & 127;
        t >>= 7;
        const int c = t & 63;
        const int b = t >> 6;

        base[s] = ((b * 256 + c) * 128 + i) * 128 + j;
        const int r = 2 * i + (j >> 6);
        ob[s] = ((b * 64 + c) * 256 + r) * 64 + (j & 63);
    }

    const int plane = 64 * 128 * 128;        // subband stride (floats)

#pragma unroll
    for (int s = 0; s < ITEMS; s++) {
#pragma unroll
        for (int k = 0; k < 4; k++)
            v[s][k] = __ldcs(x + base[s] + k * plane);
    }

#pragma unroll
    for (int s = 0; s < ITEMS; s++) {
        float o[4];
#pragma unroll
        for (int m = 0; m < 4; m++) {
            float acc = v[s][0] * fk[m];
            acc = fmaf(v[s][1], fk[4 + m], acc);
            acc = fmaf(v[s][2], fk[8 + m], acc);
            acc = fmaf(v[s][3], fk[12 + m], acc);
            o[m] = acc;
        }
        __stcs(out + ob[s], make_float4(o[0], o[1], o[2], o[3]));
    }
}

extern "C" void kernel_launch(void* const* d_in, const int* in_sizes, int n_in,
                              void* d_out, int out_size)
{
    const float* x    = (const float*)d_in[0];
    const float* filt = (const float*)d_in[1];
    float4*      out  = (float4*)d_out;

    const int blocks = HALF / BDIM;          // 16384
    idwt2d_kernel<<<blocks, BDIM>>>(x, filt, out);
}

// round 7
// speedup vs baseline: 1.1420x; 1.0316x over previous
#include <cuda_runtime.h>

// IDWT_2D (raw-reshape semantics):
//   x: (B=8, C4=256, H=128, W=128) fp32; C4 = 4 subbands (k) x 64 channels (c)
//   out[b][c][2i + (j>=64)][4*(j%64) + m] = sum_k filters[k][0][m>>1][m&1] * x[b][k*64+c][i][j]
//
// One thread per output float4, ITEMS=4 sites per thread (far-strided by
// TOTAL/4): 16 scalar loads front-batched (MLP=16), then 4 lane-contiguous
// STG.128. Streaming hints (.cs): zero reuse.

#define BDIM  256
#define ITEMS 4
#define TOTAL (8 * 64 * 128 * 128)          // output float4 count
#define CHUNK (TOTAL / ITEMS)

__global__ void __launch_bounds__(BDIM) idwt2d_kernel(
    const float* __restrict__ x,
    const float* __restrict__ filt,          // 16 coeffs: [k][a][bb] -> k*4+a*2+bb
    float4*      __restrict__ out)
{
    const int tid = blockIdx.x * BDIM + threadIdx.x;

    float fk[16];
#pragma unroll
    for (int q = 0; q < 16; q++) fk[q] = __ldg(filt + q);

    int base[ITEMS];
    int ob[ITEMS];
    float v[ITEMS][4];

#pragma unroll
    for (int s = 0; s < ITEMS; s++) {
        const int idx = tid + s * CHUNK;     // idx = ((b*64+c)*128 + i)*128 + j
        const int j = idx & 127;
        int t = idx >> 7;
        const int i = t & 127;
        t >>= 7;
        const int c = t & 63;
        const int b = t >> 6;

        base[s] = ((b * 256 + c) * 128 + i) * 128 + j;
        const int r = 2 * i + (j >> 6);
        ob[s] = ((b * 64 + c) * 256 + r) * 64 + (j & 63);
    }

    const int plane = 64 * 128 * 128;        // subband stride (floats)

    // Front-batched loads: 16 independent LDG.32 in flight
#pragma unroll
    for (int s = 0; s < ITEMS; s++) {
#pragma unroll
        for (int k = 0; k < 4; k++)
            v[s][k] = __ldcs(x + base[s] + k * plane);
    }

#pragma unroll
    for (int s = 0; s < ITEMS; s++) {
        float o[4];
#pragma unroll
        for (int m = 0; m < 4; m++) {
            float acc = v[s][0] * fk[m];
            acc = fmaf(v[s][1], fk[4 + m], acc);
            acc = fmaf(v[s][2], fk[8 + m], acc);
            acc = fmaf(v[s][3], fk[12 + m], acc);
            o[m] = acc;
        }
        __stcs(out + ob[s], make_float4(o[0], o[1], o[2], o[3]));
    }
}

extern "C" void kernel_launch(void* const* d_in, const int* in_sizes, int n_in,
                              void* d_out, int out_size)
{
    const float* x    = (const float*)d_in[0];
    const float* filt = (const float*)d_in[1];
    float4*      out  = (float4*)d_out;

    const int blocks = CHUNK / BDIM;         // 8192
    idwt2d_kernel<<<blocks, BDIM>>>(x, filt, out);
}